// round 2
// baseline (speedup 1.0000x reference)
#include <cuda_runtime.h>
#include <math.h>

#define B_TOT 4096
#define SEQ   49
#define CH    192
#define NHEAD 6
#define DH    32
#define NW    64
#define ROWS  (B_TOT * SEQ)   // 200704

// Scratch (device globals: allocation-free per harness rules)
__device__ __align__(128) float g_qkv[(size_t)ROWS * 576];
__device__ __align__(128) float g_att[(size_t)ROWS * CH];

// ---------------------------------------------------------------------------
// SGEMM: C[M,N] = A[M,K] @ B[K,N] (+ bias), fp32.
// BM=128, BN=64, BK=16, 256 threads, 8x4 microtile.
// Requires M%128==0, N%64==0, K%16==0 (true here: M=200704, N in {576,192}, K=192).
// ---------------------------------------------------------------------------
__global__ void sgemm_kernel(const float* __restrict__ A,
                             const float* __restrict__ B,
                             const float* __restrict__ bias,
                             float* __restrict__ C,
                             int M, int N, int K) {
    constexpr int BM = 128, BN = 64, BK = 16, TM = 8, TN = 4;
    __shared__ __align__(16) float As[BK][BM];
    __shared__ __align__(16) float Bs[BK][BN];

    const int tid = threadIdx.x;             // 256 threads
    const int tx  = tid & 15;                // 0..15 -> BN/TN
    const int ty  = tid >> 4;                // 0..15 -> BM/TM
    const int bm  = blockIdx.y * BM;
    const int bn  = blockIdx.x * BN;

    float acc[TM][TN];
#pragma unroll
    for (int i = 0; i < TM; i++)
#pragma unroll
        for (int j = 0; j < TN; j++) acc[i][j] = 0.0f;

    const int arow0 = tid >> 2;              // 0..63
    const int acol  = (tid & 3) * 4;         // 0,4,8,12
    const int brow  = tid >> 4;              // 0..15
    const int bcol  = (tid & 15) * 4;        // 0..60

    for (int k0 = 0; k0 < K; k0 += BK) {
        // A tile: 128x16, transposed into As[k][m]
#pragma unroll
        for (int r = 0; r < 2; r++) {
            int arow = arow0 + r * 64;
            float4 av = *(const float4*)(A + (size_t)(bm + arow) * K + k0 + acol);
            As[acol + 0][arow] = av.x;
            As[acol + 1][arow] = av.y;
            As[acol + 2][arow] = av.z;
            As[acol + 3][arow] = av.w;
        }
        // B tile: 16x64 direct
        {
            float4 bv = *(const float4*)(B + (size_t)(k0 + brow) * N + bn + bcol);
            *(float4*)&Bs[brow][bcol] = bv;
        }
        __syncthreads();

#pragma unroll
        for (int k = 0; k < BK; k++) {
            float4 a0 = *(const float4*)&As[k][ty * TM];
            float4 a1 = *(const float4*)&As[k][ty * TM + 4];
            float4 b0 = *(const float4*)&Bs[k][tx * TN];
            float ra[TM] = {a0.x, a0.y, a0.z, a0.w, a1.x, a1.y, a1.z, a1.w};
            float rb[TN] = {b0.x, b0.y, b0.z, b0.w};
#pragma unroll
            for (int i = 0; i < TM; i++)
#pragma unroll
                for (int j = 0; j < TN; j++)
                    acc[i][j] = fmaf(ra[i], rb[j], acc[i][j]);
        }
        __syncthreads();
    }

    float bv[TN] = {0.f, 0.f, 0.f, 0.f};
    if (bias) {
#pragma unroll
        for (int j = 0; j < TN; j++) bv[j] = bias[bn + tx * TN + j];
    }
#pragma unroll
    for (int i = 0; i < TM; i++) {
        int row = bm + ty * TM + i;
        float4 res;
        res.x = acc[i][0] + bv[0];
        res.y = acc[i][1] + bv[1];
        res.z = acc[i][2] + bv[2];
        res.w = acc[i][3] + bv[3];
        *(float4*)(C + (size_t)row * N + bn + tx * TN) = res;
    }
}

// ---------------------------------------------------------------------------
// Fused attention per (batch, head): scores + mask + softmax + PV.
// 64 threads/block, 8x8 grid, 7x7 register score tiles, 7x4 PV tiles.
// Rows padded to 56 so out-of-range smem reads stay in-bounds (results discarded).
// ---------------------------------------------------------------------------
__global__ void attn_kernel(const float* __restrict__ qkv,
                            const float* __restrict__ mask,
                            float* __restrict__ out) {
    const int blk = blockIdx.x;          // b * 6 + h
    const int b = blk / NHEAD;
    const int h = blk - b * NHEAD;
    const int tid = threadIdx.x;         // 64 threads

    __shared__ __align__(16) float qs[56][36];
    __shared__ __align__(16) float ks[56][36];
    __shared__ __align__(16) float vs[56][36];
    __shared__ float ss[56][57];
    __shared__ float rinv[56];

    const float scale = 0.17677669529663687f;  // 32^-0.5
    const size_t base = (size_t)b * SEQ * 576 + (size_t)h * DH;

    for (int idx = tid; idx < SEQ * DH; idx += 64) {
        int i = idx >> 5, d = idx & 31;
        size_t off = base + (size_t)i * 576 + d;
        qs[i][d] = qkv[off] * scale;
        ks[i][d] = qkv[off + 192];
        vs[i][d] = qkv[off + 384];
    }
    __syncthreads();

    const int tx = tid & 7, ty = tid >> 3;

    // Scores: S[i][j] = q[i].k[j]
    float acc[7][7];
#pragma unroll
    for (int r = 0; r < 7; r++)
#pragma unroll
        for (int c = 0; c < 7; c++) acc[r][c] = 0.0f;

#pragma unroll 4
    for (int d = 0; d < DH; d++) {
        float ra[7], rb[7];
#pragma unroll
        for (int r = 0; r < 7; r++) ra[r] = qs[ty * 7 + r][d];
#pragma unroll
        for (int c = 0; c < 7; c++) rb[c] = ks[tx * 7 + c][d];
#pragma unroll
        for (int r = 0; r < 7; r++)
#pragma unroll
            for (int c = 0; c < 7; c++)
                acc[r][c] = fmaf(ra[r], rb[c], acc[r][c]);
    }

    // Add mask, store to smem
    const float* mrow = mask + (size_t)(b & (NW - 1)) * SEQ * SEQ;
#pragma unroll
    for (int r = 0; r < 7; r++) {
        int i = ty * 7 + r;
        if (i < SEQ) {
#pragma unroll
            for (int c = 0; c < 7; c++) {
                int j = tx * 7 + c;
                if (j < SEQ) ss[i][j] = acc[r][c] + mrow[i * SEQ + j];
            }
        }
    }
    __syncthreads();

    // Softmax per row (thread i handles row i); 1/sum deferred to epilogue
    if (tid < SEQ) {
        float m = -1e30f;
#pragma unroll 7
        for (int j = 0; j < SEQ; j++) m = fmaxf(m, ss[tid][j]);
        float s = 0.0f;
#pragma unroll 7
        for (int j = 0; j < SEQ; j++) {
            float e = __expf(ss[tid][j] - m);
            ss[tid][j] = e;
            s += e;
        }
        rinv[tid] = 1.0f / s;
    }
    __syncthreads();

    // PV: out[i][d] = sum_j P[i][j] * v[j][d]
    float o[7][4];
#pragma unroll
    for (int r = 0; r < 7; r++)
#pragma unroll
        for (int c = 0; c < 4; c++) o[r][c] = 0.0f;

#pragma unroll 7
    for (int j = 0; j < SEQ; j++) {
        float pr[7];
#pragma unroll
        for (int r = 0; r < 7; r++) pr[r] = ss[ty * 7 + r][j];
        float4 vv = *(const float4*)&vs[j][tx * 4];
#pragma unroll
        for (int r = 0; r < 7; r++) {
            o[r][0] = fmaf(pr[r], vv.x, o[r][0]);
            o[r][1] = fmaf(pr[r], vv.y, o[r][1]);
            o[r][2] = fmaf(pr[r], vv.z, o[r][2]);
            o[r][3] = fmaf(pr[r], vv.w, o[r][3]);
        }
    }

#pragma unroll
    for (int r = 0; r < 7; r++) {
        int i = ty * 7 + r;
        if (i < SEQ) {
            float rs = rinv[i];
            float4 res;
            res.x = o[r][0] * rs;
            res.y = o[r][1] * rs;
            res.z = o[r][2] * rs;
            res.w = o[r][3] * rs;
            *(float4*)(out + ((size_t)b * SEQ + i) * CH + h * DH + tx * 4) = res;
        }
    }
}

// ---------------------------------------------------------------------------
extern "C" void kernel_launch(void* const* d_in, const int* in_sizes, int n_in,
                              void* d_out, int out_size) {
    const float* x      = (const float*)d_in[0];
    const float* mask   = (const float*)d_in[1];
    const float* w_qkv  = (const float*)d_in[2];
    const float* w_proj = (const float*)d_in[3];
    const float* b_proj = (const float*)d_in[4];
    float* out = (float*)d_out;

    float* qkv;
    float* att;
    cudaGetSymbolAddress((void**)&qkv, g_qkv);
    cudaGetSymbolAddress((void**)&att, g_att);

    // qkv = x @ w_qkv : (200704 x 192) @ (192 x 576)
    {
        dim3 grid(576 / 64, ROWS / 128);
        sgemm_kernel<<<grid, 256>>>(x, w_qkv, nullptr, qkv, ROWS, 576, CH);
    }
    // fused window attention
    {
        attn_kernel<<<B_TOT * NHEAD, 64>>>(qkv, mask, att);
    }
    // out = att @ w_proj + b_proj : (200704 x 192) @ (192 x 192)
    {
        dim3 grid(192 / 64, ROWS / 128);
        sgemm_kernel<<<grid, 256>>>(att, w_proj, b_proj, out, ROWS, CH, CH);
    }
}

// round 6
// speedup vs baseline: 1.7337x; 1.7337x over previous
#include <cuda_runtime.h>
#include <math.h>
#include <stdint.h>

#define B_TOT 4096
#define SEQ   49
#define CH    192
#define NHEAD 6
#define DH    32
#define NW    64
#define ROWS  (B_TOT * SEQ)   // 200704

// Scratch (device globals: allocation-free per harness rules)
__device__ __align__(128) float g_qkv[(size_t)ROWS * 576];
__device__ __align__(128) float g_att[(size_t)ROWS * CH];

__device__ __forceinline__ uint32_t f2tf32(float f) {
    uint32_t r;
    asm("cvt.rna.tf32.f32 %0, %1;" : "=r"(r) : "f"(f));
    return r;
}

__device__ __forceinline__ void mma_tf32(float c[4], const uint32_t a[4], const uint32_t b[2]) {
    asm volatile(
        "mma.sync.aligned.m16n8k8.row.col.f32.tf32.tf32.f32 "
        "{%0,%1,%2,%3}, {%4,%5,%6,%7}, {%8,%9}, {%0,%1,%2,%3};"
        : "+f"(c[0]), "+f"(c[1]), "+f"(c[2]), "+f"(c[3])
        : "r"(a[0]), "r"(a[1]), "r"(a[2]), "r"(a[3]), "r"(b[0]), "r"(b[1]));
}

// ---------------------------------------------------------------------------
// TF32 tensor-core GEMM: C[M,N] = A[M,K] @ B[K,N] (+ bias), fp32 accumulate.
// BM=128, BN=64, BK=16. 256 threads = 8 warps, warp grid 4(M) x 2(N),
// warp tile 32x32 via m16n8k8 (2 M-tiles x 4 N-tiles x 2 K-steps).
// Requires M%128==0, N%64==0, K%16==0.
// Smem layouts chosen conflict-free for fragment loads:
//   As[buf][128][20] row-major (bank = (20g+t)%32 -> 32 distinct)
//   Bs[buf][16][72]  row-major (bank = (8t+g)%32  -> 32 distinct)
// ---------------------------------------------------------------------------
__global__ __launch_bounds__(256) void tf32_gemm_kernel(
    const float* __restrict__ A,
    const float* __restrict__ B,
    const float* __restrict__ bias,
    float* __restrict__ C,
    int M, int N, int K) {

    constexpr int BM = 128, BN = 64, BK = 16;
    __shared__ uint32_t As[2][BM][20];
    __shared__ uint32_t Bs[2][BK][72];

    const int tid  = threadIdx.x;
    const int lane = tid & 31;
    const int wid  = tid >> 5;
    const int g    = lane >> 2;   // groupID 0..7
    const int t    = lane & 3;    // threadInGroup 0..3

    const int wm = (wid >> 1) * 32;   // warp M offset (0,32,64,96)
    const int wn = (wid & 1) * 32;    // warp N offset (0,32)

    const int bm = blockIdx.y * BM;
    const int bn = blockIdx.x * BN;

    // Global copy indices
    const int arow0 = tid >> 2;        // 0..63
    const int ac4   = (tid & 3) * 4;   // 0,4,8,12
    const int brow  = tid >> 4;        // 0..15
    const int bc4   = (tid & 15) * 4;  // 0..60

    float acc[2][4][4];
#pragma unroll
    for (int im = 0; im < 2; im++)
#pragma unroll
        for (int in = 0; in < 4; in++)
#pragma unroll
            for (int j = 0; j < 4; j++) acc[im][in][j] = 0.0f;

    float4 a_reg0, a_reg1, b_reg;

    // Load tile 0
    a_reg0 = *(const float4*)(A + (size_t)(bm + arow0) * K + ac4);
    a_reg1 = *(const float4*)(A + (size_t)(bm + arow0 + 64) * K + ac4);
    b_reg  = *(const float4*)(B + (size_t)brow * N + bn + bc4);

    // Store tile 0 (rounded to tf32)
    {
        uint32_t* p0 = &As[0][arow0][ac4];
        p0[0] = f2tf32(a_reg0.x); p0[1] = f2tf32(a_reg0.y);
        p0[2] = f2tf32(a_reg0.z); p0[3] = f2tf32(a_reg0.w);
        uint32_t* p1 = &As[0][arow0 + 64][ac4];
        p1[0] = f2tf32(a_reg1.x); p1[1] = f2tf32(a_reg1.y);
        p1[2] = f2tf32(a_reg1.z); p1[3] = f2tf32(a_reg1.w);
        uint32_t* pb = &Bs[0][brow][bc4];
        pb[0] = f2tf32(b_reg.x); pb[1] = f2tf32(b_reg.y);
        pb[2] = f2tf32(b_reg.z); pb[3] = f2tf32(b_reg.w);
    }
    __syncthreads();

    int buf = 0;
    for (int k0 = 0; k0 < K; k0 += BK) {
        const bool has_next = (k0 + BK) < K;
        if (has_next) {
            const int kn = k0 + BK;
            a_reg0 = *(const float4*)(A + (size_t)(bm + arow0) * K + kn + ac4);
            a_reg1 = *(const float4*)(A + (size_t)(bm + arow0 + 64) * K + kn + ac4);
            b_reg  = *(const float4*)(B + (size_t)(kn + brow) * N + bn + bc4);
        }

        // Compute on current buffer
#pragma unroll
        for (int k8 = 0; k8 < 2; k8++) {
            const int kb = k8 * 8;
            uint32_t af[2][4];
#pragma unroll
            for (int im = 0; im < 2; im++) {
                const int r0 = wm + im * 16 + g;
                af[im][0] = As[buf][r0][kb + t];
                af[im][1] = As[buf][r0 + 8][kb + t];
                af[im][2] = As[buf][r0][kb + t + 4];
                af[im][3] = As[buf][r0 + 8][kb + t + 4];
            }
            uint32_t bf[4][2];
#pragma unroll
            for (int in = 0; in < 4; in++) {
                const int n0 = wn + in * 8 + g;
                bf[in][0] = Bs[buf][kb + t][n0];
                bf[in][1] = Bs[buf][kb + t + 4][n0];
            }
#pragma unroll
            for (int im = 0; im < 2; im++)
#pragma unroll
                for (int in = 0; in < 4; in++)
                    mma_tf32(acc[im][in], af[im], bf[in]);
        }

        if (has_next) {
            const int nb = buf ^ 1;
            uint32_t* p0 = &As[nb][arow0][ac4];
            p0[0] = f2tf32(a_reg0.x); p0[1] = f2tf32(a_reg0.y);
            p0[2] = f2tf32(a_reg0.z); p0[3] = f2tf32(a_reg0.w);
            uint32_t* p1 = &As[nb][arow0 + 64][ac4];
            p1[0] = f2tf32(a_reg1.x); p1[1] = f2tf32(a_reg1.y);
            p1[2] = f2tf32(a_reg1.z); p1[3] = f2tf32(a_reg1.w);
            uint32_t* pb = &Bs[nb][brow][bc4];
            pb[0] = f2tf32(b_reg.x); pb[1] = f2tf32(b_reg.y);
            pb[2] = f2tf32(b_reg.z); pb[3] = f2tf32(b_reg.w);
        }
        __syncthreads();
        buf ^= 1;
    }

    // Epilogue: each warp writes its 32x32 tile as float2 pairs
#pragma unroll
    for (int im = 0; im < 2; im++) {
#pragma unroll
        for (int in = 0; in < 4; in++) {
            const int col = bn + wn + in * 8 + 2 * t;
            float b0 = 0.f, b1 = 0.f;
            if (bias) { b0 = bias[col]; b1 = bias[col + 1]; }
            const int r0 = bm + wm + im * 16 + g;
            float2 v0 = make_float2(acc[im][in][0] + b0, acc[im][in][1] + b1);
            float2 v1 = make_float2(acc[im][in][2] + b0, acc[im][in][3] + b1);
            *(float2*)(C + (size_t)r0 * N + col) = v0;
            *(float2*)(C + (size_t)(r0 + 8) * N + col) = v1;
        }
    }
}

// ---------------------------------------------------------------------------
// Fused attention per (batch, head): scores + mask + softmax + PV. (fp32)
// ---------------------------------------------------------------------------
__global__ void attn_kernel(const float* __restrict__ qkv,
                            const float* __restrict__ mask,
                            float* __restrict__ out) {
    const int blk = blockIdx.x;          // b * 6 + h
    const int b = blk / NHEAD;
    const int h = blk - b * NHEAD;
    const int tid = threadIdx.x;         // 64 threads

    __shared__ __align__(16) float qs[56][36];
    __shared__ __align__(16) float ks[56][36];
    __shared__ __align__(16) float vs[56][36];
    __shared__ float ss[56][57];
    __shared__ float rinv[56];

    const float scale = 0.17677669529663687f;  // 32^-0.5
    const size_t base = (size_t)b * SEQ * 576 + (size_t)h * DH;

    for (int idx = tid; idx < SEQ * DH; idx += 64) {
        int i = idx >> 5, d = idx & 31;
        size_t off = base + (size_t)i * 576 + d;
        qs[i][d] = qkv[off] * scale;
        ks[i][d] = qkv[off + 192];
        vs[i][d] = qkv[off + 384];
    }
    __syncthreads();

    const int tx = tid & 7, ty = tid >> 3;

    float acc[7][7];
#pragma unroll
    for (int r = 0; r < 7; r++)
#pragma unroll
        for (int c = 0; c < 7; c++) acc[r][c] = 0.0f;

#pragma unroll 4
    for (int d = 0; d < DH; d++) {
        float ra[7], rb[7];
#pragma unroll
        for (int r = 0; r < 7; r++) ra[r] = qs[ty * 7 + r][d];
#pragma unroll
        for (int c = 0; c < 7; c++) rb[c] = ks[tx * 7 + c][d];
#pragma unroll
        for (int r = 0; r < 7; r++)
#pragma unroll
            for (int c = 0; c < 7; c++)
                acc[r][c] = fmaf(ra[r], rb[c], acc[r][c]);
    }

    const float* mrow = mask + (size_t)(b & (NW - 1)) * SEQ * SEQ;
#pragma unroll
    for (int r = 0; r < 7; r++) {
        int i = ty * 7 + r;
        if (i < SEQ) {
#pragma unroll
            for (int c = 0; c < 7; c++) {
                int j = tx * 7 + c;
                if (j < SEQ) ss[i][j] = acc[r][c] + mrow[i * SEQ + j];
            }
        }
    }
    __syncthreads();

    if (tid < SEQ) {
        float m = -1e30f;
#pragma unroll 7
        for (int j = 0; j < SEQ; j++) m = fmaxf(m, ss[tid][j]);
        float s = 0.0f;
#pragma unroll 7
        for (int j = 0; j < SEQ; j++) {
            float e = __expf(ss[tid][j] - m);
            ss[tid][j] = e;
            s += e;
        }
        rinv[tid] = 1.0f / s;
    }
    __syncthreads();

    float o[7][4];
#pragma unroll
    for (int r = 0; r < 7; r++)
#pragma unroll
        for (int c = 0; c < 4; c++) o[r][c] = 0.0f;

#pragma unroll 7
    for (int j = 0; j < SEQ; j++) {
        float pr[7];
#pragma unroll
        for (int r = 0; r < 7; r++) pr[r] = ss[ty * 7 + r][j];
        float4 vv = *(const float4*)&vs[j][tx * 4];
#pragma unroll
        for (int r = 0; r < 7; r++) {
            o[r][0] = fmaf(pr[r], vv.x, o[r][0]);
            o[r][1] = fmaf(pr[r], vv.y, o[r][1]);
            o[r][2] = fmaf(pr[r], vv.z, o[r][2]);
            o[r][3] = fmaf(pr[r], vv.w, o[r][3]);
        }
    }

#pragma unroll
    for (int r = 0; r < 7; r++) {
        int i = ty * 7 + r;
        if (i < SEQ) {
            float rs = rinv[i];
            float4 res;
            res.x = o[r][0] * rs;
            res.y = o[r][1] * rs;
            res.z = o[r][2] * rs;
            res.w = o[r][3] * rs;
            *(float4*)(out + ((size_t)b * SEQ + i) * CH + h * DH + tx * 4) = res;
        }
    }
}

// ---------------------------------------------------------------------------
extern "C" void kernel_launch(void* const* d_in, const int* in_sizes, int n_in,
                              void* d_out, int out_size) {
    const float* x      = (const float*)d_in[0];
    const float* mask   = (const float*)d_in[1];
    const float* w_qkv  = (const float*)d_in[2];
    const float* w_proj = (const float*)d_in[3];
    const float* b_proj = (const float*)d_in[4];
    float* out = (float*)d_out;

    float* qkv;
    float* att;
    cudaGetSymbolAddress((void**)&qkv, g_qkv);
    cudaGetSymbolAddress((void**)&att, g_att);

    // qkv = x @ w_qkv : (200704 x 192) @ (192 x 576)
    {
        dim3 grid(576 / 64, ROWS / 128);
        tf32_gemm_kernel<<<grid, 256>>>(x, w_qkv, nullptr, qkv, ROWS, 576, CH);
    }
    // fused window attention
    {
        attn_kernel<<<B_TOT * NHEAD, 64>>>(qkv, mask, g_att ? att : att);
    }
    // out = att @ w_proj + b_proj : (200704 x 192) @ (192 x 192)
    {
        dim3 grid(192 / 64, ROWS / 128);
        tf32_gemm_kernel<<<grid, 256>>>(att, w_proj, b_proj, out, ROWS, CH, CH);
    }
}

// round 8
// speedup vs baseline: 1.7534x; 1.0113x over previous
#include <cuda_runtime.h>
#include <math.h>
#include <stdint.h>

#define B_TOT 4096
#define SEQ   49
#define CH    192
#define NHEAD 6
#define DH    32
#define NW    64
#define ROWS  (B_TOT * SEQ)   // 200704

__device__ __align__(128) float g_qkv[(size_t)ROWS * 576];
__device__ __align__(128) float g_att[(size_t)ROWS * CH];

__device__ __forceinline__ uint32_t f2tf32(float f) {
    uint32_t r;
    asm("cvt.rna.tf32.f32 %0, %1;" : "=r"(r) : "f"(f));
    return r;
}

__device__ __forceinline__ void mma_tf32(float c[4], const uint32_t a[4], const uint32_t b[2]) {
    asm volatile(
        "mma.sync.aligned.m16n8k8.row.col.f32.tf32.tf32.f32 "
        "{%0,%1,%2,%3}, {%4,%5,%6,%7}, {%8,%9}, {%0,%1,%2,%3};"
        : "+f"(c[0]), "+f"(c[1]), "+f"(c[2]), "+f"(c[3])
        : "r"(a[0]), "r"(a[1]), "r"(a[2]), "r"(a[3]), "r"(b[0]), "r"(b[1]));
}

// ---------------------------------------------------------------------------
// TF32 tensor-core GEMM: C[M,N] = A[M,K] @ B[K,N] (+ bias), fp32 accumulate.
// BM=128, BN=64, BK=16, 128 threads = 4 warps, warp grid 2(M) x 2(N),
// warp tile 64x32 (4 M-subtiles x 4 N-subtiles of m16n8k8, 2 K-steps).
//
// A smem: k-pair interleaved so (col t, col t+4) are adjacent -> LDS.64 frags.
//   word(c) = (c>>3)*8 + 2*(c&3) + ((c>>2)&1), row stride 24 words.
//   Frag addr = r*24 + k8*8 + 2t -> half-warp covers 32 distinct banks.
// B smem: [k][n ^ ((k&3)<<3)], stride 64 -> frag banks 8*((n0/8 ^ t)&3)+g,
//   full-warp conflict-free.
// ---------------------------------------------------------------------------
template<int K>
__global__ __launch_bounds__(128) void tf32_gemm_kernel(
    const float* __restrict__ A,
    const float* __restrict__ B,
    const float* __restrict__ bias,
    float* __restrict__ C,
    int M, int N) {

    constexpr int BM = 128, BN = 64, BK = 16;
    constexpr int ASTR = 24;
    __shared__ uint32_t As[2][BM * ASTR];
    __shared__ uint32_t Bs[2][BK * BN];

    const int tid  = threadIdx.x;        // 128 threads
    const int lane = tid & 31;
    const int wid  = tid >> 5;
    const int g    = lane >> 2;          // 0..7
    const int t    = lane & 3;           // 0..3

    const int wm = (wid >> 1) * 64;      // 0 or 64
    const int wn = (wid & 1) * 32;       // 0 or 32

    const int bm = blockIdx.y * BM;
    const int bn = blockIdx.x * BN;

    // A copy: 2048 words / 128 thr = 4 rows x 1 float4 each
    const int arow0 = tid >> 2;          // 0..31 (+32r)
    const int ac4   = (tid & 3) * 4;     // 0,4,8,12
    const int apos0 = ((ac4 >> 3) << 3) + ((ac4 >> 2) & 1);  // word base in row
    // B copy: 1024 words / 128 thr = 2 float4 per thread
    const int brow  = tid >> 3;          // 0..15
    const int bc8   = (tid & 7) * 8;     // 0..56
    const int bxor  = (brow & 3) << 3;

    float acc[4][4][4];
#pragma unroll
    for (int im = 0; im < 4; im++)
#pragma unroll
        for (int in = 0; in < 4; in++)
#pragma unroll
            for (int j = 0; j < 4; j++) acc[im][in][j] = 0.0f;

    float4 pa[4], pb[2];

    // ---- load tile 0 ----
#pragma unroll
    for (int r = 0; r < 4; r++)
        pa[r] = *(const float4*)(A + (size_t)(bm + arow0 + r * 32) * K + ac4);
    pb[0] = *(const float4*)(B + (size_t)brow * N + bn + bc8);
    pb[1] = *(const float4*)(B + (size_t)brow * N + bn + bc8 + 4);

#pragma unroll
    for (int r = 0; r < 4; r++) {
        uint32_t* p = &As[0][(arow0 + r * 32) * ASTR + apos0];
        p[0] = f2tf32(pa[r].x); p[2] = f2tf32(pa[r].y);
        p[4] = f2tf32(pa[r].z); p[6] = f2tf32(pa[r].w);
    }
    {
        uint32_t* p0 = &Bs[0][brow * BN + (bc8 ^ bxor)];
        p0[0] = f2tf32(pb[0].x); p0[1] = f2tf32(pb[0].y);
        p0[2] = f2tf32(pb[0].z); p0[3] = f2tf32(pb[0].w);
        uint32_t* p1 = &Bs[0][brow * BN + ((bc8 + 4) ^ bxor)];
        p1[0] = f2tf32(pb[1].x); p1[1] = f2tf32(pb[1].y);
        p1[2] = f2tf32(pb[1].z); p1[3] = f2tf32(pb[1].w);
    }
    __syncthreads();

    int buf = 0;
#pragma unroll
    for (int k0 = 0; k0 < K; k0 += BK) {
        const bool has_next = (k0 + BK) < K;
        if (has_next) {
            const int kn = k0 + BK;
#pragma unroll
            for (int r = 0; r < 4; r++)
                pa[r] = *(const float4*)(A + (size_t)(bm + arow0 + r * 32) * K + kn + ac4);
            pb[0] = *(const float4*)(B + (size_t)(kn + brow) * N + bn + bc8);
            pb[1] = *(const float4*)(B + (size_t)(kn + brow) * N + bn + bc8 + 4);
        }

#pragma unroll
        for (int k8 = 0; k8 < 2; k8++) {
            const int kb = k8 * 8;
            uint32_t af[4][4];
#pragma unroll
            for (int im = 0; im < 4; im++) {
                const int r0 = wm + im * 16 + g;
                uint2 q0 = *(const uint2*)&As[buf][r0 * ASTR + kb + 2 * t];
                uint2 q1 = *(const uint2*)&As[buf][(r0 + 8) * ASTR + kb + 2 * t];
                af[im][0] = q0.x; af[im][2] = q0.y;   // (row g,  col t), (row g,  col t+4)
                af[im][1] = q1.x; af[im][3] = q1.y;   // (row g+8,col t), (row g+8,col t+4)
            }
            uint32_t bf[4][2];
#pragma unroll
            for (int in = 0; in < 4; in++) {
                const int n0 = wn + in * 8 + g;
                bf[in][0] = Bs[buf][(kb + t) * BN + (n0 ^ ((t & 3) << 3))];
                bf[in][1] = Bs[buf][(kb + t + 4) * BN + (n0 ^ (((t + 4) & 3) << 3))];
            }
#pragma unroll
            for (int im = 0; im < 4; im++)
#pragma unroll
                for (int in = 0; in < 4; in++)
                    mma_tf32(acc[im][in], af[im], bf[in]);
        }

        if (has_next) {
            const int nb = buf ^ 1;
#pragma unroll
            for (int r = 0; r < 4; r++) {
                uint32_t* p = &As[nb][(arow0 + r * 32) * ASTR + apos0];
                p[0] = f2tf32(pa[r].x); p[2] = f2tf32(pa[r].y);
                p[4] = f2tf32(pa[r].z); p[6] = f2tf32(pa[r].w);
            }
            uint32_t* p0 = &Bs[nb][brow * BN + (bc8 ^ bxor)];
            p0[0] = f2tf32(pb[0].x); p0[1] = f2tf32(pb[0].y);
            p0[2] = f2tf32(pb[0].z); p0[3] = f2tf32(pb[0].w);
            uint32_t* p1 = &Bs[nb][brow * BN + ((bc8 + 4) ^ bxor)];
            p1[0] = f2tf32(pb[1].x); p1[1] = f2tf32(pb[1].y);
            p1[2] = f2tf32(pb[1].z); p1[3] = f2tf32(pb[1].w);
        }
        __syncthreads();
        buf ^= 1;
    }

    // Epilogue
#pragma unroll
    for (int im = 0; im < 4; im++) {
#pragma unroll
        for (int in = 0; in < 4; in++) {
            const int col = bn + wn + in * 8 + 2 * t;
            float b0 = 0.f, b1 = 0.f;
            if (bias) { b0 = bias[col]; b1 = bias[col + 1]; }
            const int r0 = bm + wm + im * 16 + g;
            float2 v0 = make_float2(acc[im][in][0] + b0, acc[im][in][1] + b1);
            float2 v1 = make_float2(acc[im][in][2] + b0, acc[im][in][3] + b1);
            *(float2*)(C + (size_t)r0 * N + col) = v0;
            *(float2*)(C + (size_t)(r0 + 8) * N + col) = v1;
        }
    }
}

// ---------------------------------------------------------------------------
// Fused attention per (batch, head). 64 threads. Smem overlay: the P buffer
// (ss) reuses the q/k region (dead after the score phase). Arrays are exactly
// 49 rows; out-of-tile thread rows are clamped (results discarded).
// ---------------------------------------------------------------------------
#define QS_STR 33
#define SS_STR 53
#define VS_STR 36

__global__ __launch_bounds__(64) void attn_kernel(
    const float* __restrict__ qkv,
    const float* __restrict__ mask,
    float* __restrict__ out) {
    const int blk = blockIdx.x;          // b * 6 + h
    const int b = blk / NHEAD;
    const int h = blk - b * NHEAD;
    const int tid = threadIdx.x;         // 64 threads

    __shared__ __align__(16) float pool[SEQ * QS_STR * 2];   // qs+ks, later ss
    __shared__ __align__(16) float vs[SEQ * VS_STR];
    __shared__ float rinv[SEQ];

    float* qs = pool;
    float* ks = pool + SEQ * QS_STR;
    float* ss = pool;                    // overlays qs/ks after score phase

    const float scale = 0.17677669529663687f;  // 32^-0.5
    const size_t base = (size_t)b * SEQ * 576 + (size_t)h * DH;

    for (int idx = tid; idx < SEQ * DH; idx += 64) {
        int i = idx >> 5, d = idx & 31;
        size_t off = base + (size_t)i * 576 + d;
        qs[i * QS_STR + d] = qkv[off] * scale;
        ks[i * QS_STR + d] = qkv[off + 192];
        vs[i * VS_STR + d] = qkv[off + 384];
    }
    __syncthreads();

    const int tx = tid & 7, ty = tid >> 3;

    int qrow[7], kcol[7];
#pragma unroll
    for (int r = 0; r < 7; r++) {
        int i = ty * 7 + r; qrow[r] = (i < SEQ ? i : SEQ - 1) * QS_STR;
        int j = tx * 7 + r; kcol[r] = (j < SEQ ? j : SEQ - 1) * QS_STR;
    }

    float acc[7][7];
#pragma unroll
    for (int r = 0; r < 7; r++)
#pragma unroll
        for (int c = 0; c < 7; c++) acc[r][c] = 0.0f;

#pragma unroll 4
    for (int d = 0; d < DH; d++) {
        float ra[7], rb[7];
#pragma unroll
        for (int r = 0; r < 7; r++) ra[r] = qs[qrow[r] + d];
#pragma unroll
        for (int c = 0; c < 7; c++) rb[c] = ks[kcol[c] + d];
#pragma unroll
        for (int r = 0; r < 7; r++)
#pragma unroll
            for (int c = 0; c < 7; c++)
                acc[r][c] = fmaf(ra[r], rb[c], acc[r][c]);
    }
    __syncthreads();   // all q/k reads done before ss overlays them

    const float* mrow = mask + (size_t)(b & (NW - 1)) * SEQ * SEQ;
#pragma unroll
    for (int r = 0; r < 7; r++) {
        int i = ty * 7 + r;
        if (i < SEQ) {
#pragma unroll
            for (int c = 0; c < 7; c++) {
                int j = tx * 7 + c;
                if (j < SEQ) ss[i * SS_STR + j] = acc[r][c] + mrow[i * SEQ + j];
            }
        }
    }
    __syncthreads();

    if (tid < SEQ) {
        float m = -1e30f;
#pragma unroll 7
        for (int j = 0; j < SEQ; j++) m = fmaxf(m, ss[tid * SS_STR + j]);
        float s = 0.0f;
#pragma unroll 7
        for (int j = 0; j < SEQ; j++) {
            float e = __expf(ss[tid * SS_STR + j] - m);
            ss[tid * SS_STR + j] = e;
            s += e;
        }
        rinv[tid] = 1.0f / s;
    }
    __syncthreads();

    int srow[7];
#pragma unroll
    for (int r = 0; r < 7; r++) {
        int i = ty * 7 + r; srow[r] = (i < SEQ ? i : SEQ - 1) * SS_STR;
    }

    float o[7][4];
#pragma unroll
    for (int r = 0; r < 7; r++)
#pragma unroll
        for (int c = 0; c < 4; c++) o[r][c] = 0.0f;

#pragma unroll 7
    for (int j = 0; j < SEQ; j++) {
        float pr[7];
#pragma unroll
        for (int r = 0; r < 7; r++) pr[r] = ss[srow[r] + j];
        float4 vv = *(const float4*)&vs[j * VS_STR + tx * 4];
#pragma unroll
        for (int r = 0; r < 7; r++) {
            o[r][0] = fmaf(pr[r], vv.x, o[r][0]);
            o[r][1] = fmaf(pr[r], vv.y, o[r][1]);
            o[r][2] = fmaf(pr[r], vv.z, o[r][2]);
            o[r][3] = fmaf(pr[r], vv.w, o[r][3]);
        }
    }

#pragma unroll
    for (int r = 0; r < 7; r++) {
        int i = ty * 7 + r;
        if (i < SEQ) {
            float rs = rinv[i];
            float4 res;
            res.x = o[r][0] * rs;
            res.y = o[r][1] * rs;
            res.z = o[r][2] * rs;
            res.w = o[r][3] * rs;
            *(float4*)(out + ((size_t)b * SEQ + i) * CH + h * DH + tx * 4) = res;
        }
    }
}

// ---------------------------------------------------------------------------
extern "C" void kernel_launch(void* const* d_in, const int* in_sizes, int n_in,
                              void* d_out, int out_size) {
    const float* x      = (const float*)d_in[0];
    const float* mask   = (const float*)d_in[1];
    const float* w_qkv  = (const float*)d_in[2];
    const float* w_proj = (const float*)d_in[3];
    const float* b_proj = (const float*)d_in[4];
    float* out = (float*)d_out;

    float* qkv;
    float* att;
    cudaGetSymbolAddress((void**)&qkv, g_qkv);
    cudaGetSymbolAddress((void**)&att, g_att);

    // qkv = x @ w_qkv : (200704 x 192) @ (192 x 576)
    {
        dim3 grid(576 / 64, ROWS / 128);
        tf32_gemm_kernel<192><<<grid, 128>>>(x, w_qkv, nullptr, qkv, ROWS, 576);
    }
    // fused window attention
    {
        attn_kernel<<<B_TOT * NHEAD, 64>>>(qkv, mask, att);
    }
    // out = att @ w_proj + b_proj : (200704 x 192) @ (192 x 192)
    {
        dim3 grid(192 / 64, ROWS / 128);
        tf32_gemm_kernel<192><<<grid, 128>>>(att, w_proj, b_proj, out, ROWS, CH);
    }
}